// round 1
// baseline (speedup 1.0000x reference)
#include <cuda_runtime.h>
#include <math.h>
#include <stdint.h>

#define N_NODES 50000
#define N_EDGES 800000

// ---------------- scratch (static device allocations; no cudaMalloc) ------
// 4 buffers x 50000 x 1024 fp32 = 4 x 204.8 MB
__device__ float g_z[(size_t)N_NODES * 1024];
__device__ float g_t[(size_t)N_NODES * 1024];
__device__ float g_r[(size_t)N_NODES * 1024];
__device__ float g_h[(size_t)N_NODES * 1024];

// ---------------- elementwise copy (z <- h) --------------------------------
__global__ void copy_kernel(const float4* __restrict__ src, float4* __restrict__ dst, long n4) {
    long i = (long)blockIdx.x * 256 + threadIdx.x;
    if (i < n4) dst[i] = src[i];
}

// ---------------- edge scatter: z[dst] += h[src] ---------------------------
// one thread per (edge, 4-feature chunk); consecutive threads share an edge
__global__ void scatter_kernel(const float* __restrict__ h, const int* __restrict__ ei,
                               float* __restrict__ z, unsigned per /*D/4*/, int D) {
    unsigned tid = blockIdx.x * 256u + threadIdx.x;
    unsigned total = (unsigned)N_EDGES * per;
    if (tid >= total) return;
    unsigned e = tid / per;
    unsigned f = tid % per;
    int src = __ldg(ei + e);
    int dst = __ldg(ei + N_EDGES + e);
    float4 v = *(const float4*)(h + (size_t)src * D + f * 4);
    float* zp = z + (size_t)dst * D + f * 4;
    atomicAdd(zp + 0, v.x);
    atomicAdd(zp + 1, v.y);
    atomicAdd(zp + 2, v.z);
    atomicAdd(zp + 3, v.w);
}

// ---------------- fp32 tiled GEMM: C = op(A[NxK] @ W[KxDO] + bias [, R]) ---
// MODE 0: C = A@W + bias
// MODE 1: C = relu(A@W + bias)
// MODE 2: C = relu( relu(A@W + bias) + R )   (inner MLP relu, then residual relu)
template <int MODE>
__global__ void __launch_bounds__(256, 2)
gemm_kernel(const float* __restrict__ A, const float* __restrict__ W,
            const float* __restrict__ bias, const float* __restrict__ Radd,
            float* __restrict__ C, int N, int K, int DO) {
    constexpr int BM = 128, BN = 128, BK = 8;
    __shared__ float  As[BK][BM + 4];      // +4 pad keeps 16B alignment, reduces conflicts
    __shared__ float4 Bs[BK][BN / 4];

    const int tid = threadIdx.x;
    const int tx = tid & 15;          // 0..15 -> 8 output cols each
    const int ty = tid >> 4;          // 0..15 -> 8 output rows each
    const int bm = blockIdx.x * BM;
    const int bn = blockIdx.y * BN;

    // A-tile loader: thread loads one float4; a_m = row in tile, a_k = k offset
    const int a_m = tid >> 1;
    const int a_k = (tid & 1) * 4;
    // B-tile loader: thread loads one float4 of W row
    const int b_k  = tid >> 5;
    const int b_n4 = tid & 31;

    const int arow = bm + a_m;
    const bool aok = arow < N;
    const float* Aptr = A + (size_t)arow * K + a_k;
    const float* Wptr = W + (size_t)b_k * DO + bn + b_n4 * 4;

    float acc[8][8];
#pragma unroll
    for (int i = 0; i < 8; i++)
#pragma unroll
        for (int j = 0; j < 8; j++) acc[i][j] = 0.f;

    for (int k0 = 0; k0 < K; k0 += BK) {
        float4 av = aok ? *(const float4*)(Aptr + k0) : make_float4(0.f, 0.f, 0.f, 0.f);
        As[a_k + 0][a_m] = av.x;
        As[a_k + 1][a_m] = av.y;
        As[a_k + 2][a_m] = av.z;
        As[a_k + 3][a_m] = av.w;
        Bs[b_k][b_n4] = *(const float4*)(Wptr + (size_t)k0 * DO);
        __syncthreads();

#pragma unroll
        for (int kk = 0; kk < BK; kk++) {
            float4 a0 = *(const float4*)&As[kk][ty * 8];
            float4 a1 = *(const float4*)&As[kk][ty * 8 + 4];
            float4 b0 = Bs[kk][tx * 2];
            float4 b1 = Bs[kk][tx * 2 + 1];
            float ar[8] = {a0.x, a0.y, a0.z, a0.w, a1.x, a1.y, a1.z, a1.w};
            float br[8] = {b0.x, b0.y, b0.z, b0.w, b1.x, b1.y, b1.z, b1.w};
#pragma unroll
            for (int i = 0; i < 8; i++)
#pragma unroll
                for (int j = 0; j < 8; j++)
                    acc[i][j] = fmaf(ar[i], br[j], acc[i][j]);
        }
        __syncthreads();
    }

    // epilogue
    const int cm = bm + ty * 8;
    const int cn = bn + tx * 8;
    float4 bv0 = *(const float4*)(bias + cn);
    float4 bv1 = *(const float4*)(bias + cn + 4);
    const float bb[8] = {bv0.x, bv0.y, bv0.z, bv0.w, bv1.x, bv1.y, bv1.z, bv1.w};

#pragma unroll
    for (int i = 0; i < 8; i++) {
        int rrow = cm + i;
        if (rrow >= N) break;
        float o[8];
#pragma unroll
        for (int j = 0; j < 8; j++) o[j] = acc[i][j] + bb[j];
        if (MODE >= 1) {
#pragma unroll
            for (int j = 0; j < 8; j++) o[j] = fmaxf(o[j], 0.f);
        }
        if (MODE == 2) {
            const float* rp = Radd + (size_t)rrow * DO + cn;
            float4 r0 = *(const float4*)(rp);
            float4 r1 = *(const float4*)(rp + 4);
            float rr[8] = {r0.x, r0.y, r0.z, r0.w, r1.x, r1.y, r1.z, r1.w};
#pragma unroll
            for (int j = 0; j < 8; j++) o[j] = fmaxf(o[j] + rr[j], 0.f);
        }
        float* cp = C + (size_t)rrow * DO + cn;
        *(float4*)(cp)     = make_float4(o[0], o[1], o[2], o[3]);
        *(float4*)(cp + 4) = make_float4(o[4], o[5], o[6], o[7]);
    }
}

// ---------------- row LayerNorm: out = (x-mu)*rsqrt(var+eps)*g + b ---------
__global__ void ln_kernel(const float* __restrict__ in, const float* __restrict__ gam,
                          const float* __restrict__ bet, float* __restrict__ out, int D) {
    const int row = blockIdx.x;
    const float4* ip = (const float4*)(in + (size_t)row * D);
    float4* op = (float4*)(out + (size_t)row * D);
    const int nv = D >> 2;  // 64..256 float4s

    float4 v[4];
    int cnt = 0;
    float s = 0.f, ss = 0.f;
    for (int i = threadIdx.x; i < nv; i += 256) {
        float4 x = ip[i];
        v[cnt++] = x;
        s  += x.x + x.y + x.z + x.w;
        ss += x.x * x.x + x.y * x.y + x.z * x.z + x.w * x.w;
    }
#pragma unroll
    for (int o = 16; o; o >>= 1) {
        s  += __shfl_xor_sync(0xffffffffu, s, o);
        ss += __shfl_xor_sync(0xffffffffu, ss, o);
    }
    __shared__ float rs[8], rss[8], stats[2];
    const int w = threadIdx.x >> 5, l = threadIdx.x & 31;
    if (l == 0) { rs[w] = s; rss[w] = ss; }
    __syncthreads();
    if (threadIdx.x < 32) {
        float a = (threadIdx.x < 8) ? rs[threadIdx.x]  : 0.f;
        float b = (threadIdx.x < 8) ? rss[threadIdx.x] : 0.f;
#pragma unroll
        for (int o = 4; o; o >>= 1) {
            a += __shfl_xor_sync(0xffffffffu, a, o);
            b += __shfl_xor_sync(0xffffffffu, b, o);
        }
        if (threadIdx.x == 0) {
            float mu  = a / (float)D;
            float var = b / (float)D - mu * mu;
            stats[0] = mu;
            stats[1] = rsqrtf(var + 1e-5f);
        }
    }
    __syncthreads();
    const float mu = stats[0], inv = stats[1];
    cnt = 0;
    for (int i = threadIdx.x; i < nv; i += 256) {
        float4 x = v[cnt++];
        float4 g = ((const float4*)gam)[i];
        float4 b = ((const float4*)bet)[i];
        float4 o;
        o.x = (x.x - mu) * inv * g.x + b.x;
        o.y = (x.y - mu) * inv * g.y + b.y;
        o.z = (x.z - mu) * inv * g.z + b.z;
        o.w = (x.w - mu) * inv * g.w + b.w;
        op[i] = o;
    }
}

// ---------------- host orchestration --------------------------------------
static void run_block(const float* hin, int d, int dout, const int* ei,
                      const float* wa, const float* ba, const float* wb, const float* bb,
                      const float* rw, const float* rb, const float* lg, const float* lb,
                      float* z, float* t, float* r, float* hout) {
    // z = hin
    long n4 = (long)N_NODES * d / 4;
    copy_kernel<<<(unsigned)((n4 + 255) / 256), 256>>>((const float4*)hin, (float4*)z, n4);
    // z += scatter_add(hin[src] -> dst)
    unsigned per = (unsigned)(d / 4);
    unsigned tot = (unsigned)N_EDGES * per;
    scatter_kernel<<<(tot + 255u) / 256u, 256>>>(hin, ei, z, per, d);

    dim3 grid((N_NODES + 127) / 128, dout / 128);
    // t = relu(z @ wa + ba)
    gemm_kernel<1><<<grid, 256>>>(z, wa, ba, nullptr, t, N_NODES, d, dout);
    // r = hin @ rw + rb
    gemm_kernel<0><<<grid, 256>>>(hin, rw, rb, nullptr, r, N_NODES, d, dout);
    // z = relu( relu(t @ wb + bb) + r )      (reuse z as pre-LN buffer)
    gemm_kernel<2><<<grid, 256>>>(t, wb, bb, r, z, N_NODES, dout, dout);
    // hout = LN(z)
    ln_kernel<<<N_NODES, 256>>>(z, lg, lb, hout, dout);
}

extern "C" void kernel_launch(void* const* d_in, const int* in_sizes, int n_in,
                              void* d_out, int out_size) {
    const float* x   = (const float*)d_in[0];
    const int*   ei  = (const int*)d_in[1];
    const float* w1a = (const float*)d_in[2];
    const float* b1a = (const float*)d_in[3];
    const float* w1b = (const float*)d_in[4];
    const float* b1b = (const float*)d_in[5];
    const float* w2a = (const float*)d_in[6];
    const float* b2a = (const float*)d_in[7];
    const float* w2b = (const float*)d_in[8];
    const float* b2b = (const float*)d_in[9];
    const float* w3a = (const float*)d_in[10];
    const float* b3a = (const float*)d_in[11];
    const float* w3b = (const float*)d_in[12];
    const float* b3b = (const float*)d_in[13];
    const float* rp1w = (const float*)d_in[14];
    const float* rp1b = (const float*)d_in[15];
    const float* rp2w = (const float*)d_in[16];
    const float* rp2b = (const float*)d_in[17];
    const float* rp3w = (const float*)d_in[18];
    const float* rp3b = (const float*)d_in[19];
    const float* ln1g = (const float*)d_in[20];
    const float* ln1b = (const float*)d_in[21];
    const float* ln2g = (const float*)d_in[22];
    const float* ln2b = (const float*)d_in[23];
    const float* ln3g = (const float*)d_in[24];
    const float* ln3b = (const float*)d_in[25];
    float* out = (float*)d_out;

    float *z, *t, *r, *h;
    cudaGetSymbolAddress((void**)&z, g_z);
    cudaGetSymbolAddress((void**)&t, g_t);
    cudaGetSymbolAddress((void**)&r, g_r);
    cudaGetSymbolAddress((void**)&h, g_h);

    // block 1: 128 -> 256
    run_block(x, 128, 256, ei, w1a, b1a, w1b, b1b, rp1w, rp1b, ln1g, ln1b, z, t, r, h);
    // block 2: 256 -> 512
    run_block(h, 256, 512, ei, w2a, b2a, w2b, b2b, rp2w, rp2b, ln2g, ln2b, z, t, r, h);
    // block 3: 512 -> 1024, final LN writes d_out
    run_block(h, 512, 1024, ei, w3a, b3a, w3b, b3b, rp3w, rp3b, ln3g, ln3b, z, t, r, out);
}

// round 3
// speedup vs baseline: 1.9753x; 1.9753x over previous
#include <cuda_runtime.h>
#include <cuda_bf16.h>
#include <math.h>
#include <stdint.h>

#define N_NODES 50000
#define N_EDGES 800000

// ---------------- scratch (static device arrays; no cudaMalloc) -----------
__device__ float g_z[(size_t)N_NODES * 1024];
__device__ float g_t[(size_t)N_NODES * 1024];
__device__ float g_r[(size_t)N_NODES * 1024];
__device__ float g_h[(size_t)N_NODES * 1024];
__device__ __nv_bfloat16 g_a1hi[(size_t)N_NODES * 1024];
__device__ __nv_bfloat16 g_a1lo[(size_t)N_NODES * 1024];
__device__ __nv_bfloat16 g_a2hi[(size_t)N_NODES * 1024];
__device__ __nv_bfloat16 g_a2lo[(size_t)N_NODES * 1024];
#define W_TOTAL 2752512
__device__ __nv_bfloat16 g_whi[W_TOTAL];
__device__ __nv_bfloat16 g_wlo[W_TOTAL];

// ============================ PTX helpers ==================================
__device__ __forceinline__ uint32_t smem_u32(const void* p) {
    uint32_t a;
    asm("{ .reg .u64 t; cvta.to.shared.u64 t, %1; cvt.u32.u64 %0, t; }" : "=r"(a) : "l"(p));
    return a;
}
__device__ __forceinline__ void cp16(uint32_t dst, const void* src, bool ok) {
    int sz = ok ? 16 : 0;
    asm volatile("cp.async.cg.shared.global [%0], [%1], 16, %2;" :: "r"(dst), "l"(src), "r"(sz) : "memory");
}
#define CP_COMMIT() asm volatile("cp.async.commit_group;" ::: "memory")

#define LDSM4(r0, r1, r2, r3, addr) \
    asm volatile("ldmatrix.sync.aligned.m8n8.x4.shared.b16 {%0,%1,%2,%3}, [%4];" \
                 : "=r"(r0), "=r"(r1), "=r"(r2), "=r"(r3) : "r"(addr))

#define MMA16816(d, a, b) \
    asm volatile("mma.sync.aligned.m16n8k16.row.col.f32.bf16.bf16.f32 " \
                 "{%0,%1,%2,%3}, {%4,%5,%6,%7}, {%8,%9}, {%0,%1,%2,%3};" \
                 : "+f"((d)[0]), "+f"((d)[1]), "+f"((d)[2]), "+f"((d)[3]) \
                 : "r"((a)[0]), "r"((a)[1]), "r"((a)[2]), "r"((a)[3]), "r"((b)[0]), "r"((b)[1]))

// ---------------- elementwise copy -----------------------------------------
__global__ void copy_kernel(const float4* __restrict__ src, float4* __restrict__ dst, long n4) {
    long i = (long)blockIdx.x * 256 + threadIdx.x;
    if (i < n4) dst[i] = src[i];
}

// ---------------- edge scatter: z[dst] += h[src] (v4 red) -------------------
__global__ void scatter_kernel(const float* __restrict__ h, const int* __restrict__ ei,
                               float* __restrict__ z, unsigned per, int D) {
    unsigned tid = blockIdx.x * 256u + threadIdx.x;
    unsigned total = (unsigned)N_EDGES * per;
    if (tid >= total) return;
    unsigned e = tid / per;
    unsigned f = tid % per;
    int src = __ldg(ei + e);
    int dst = __ldg(ei + N_EDGES + e);
    float4 v = *(const float4*)(h + (size_t)src * D + f * 4);
    float* zp = z + (size_t)dst * D + f * 4;
    asm volatile("red.global.add.v4.f32 [%0], {%1,%2,%3,%4};"
                 :: "l"(zp), "f"(v.x), "f"(v.y), "f"(v.z), "f"(v.w) : "memory");
}

// ---------------- weight transpose + hi/lo split ----------------------------
// in:  W[K][DO] fp32   out: Wt_hi/Wt_lo [DO][K] bf16
__global__ void wsplit_kernel(const float* __restrict__ W,
                              __nv_bfloat16* __restrict__ hi, __nv_bfloat16* __restrict__ lo,
                              int K, int DO) {
    __shared__ float s[32][33];
    int tx = threadIdx.x, ty = threadIdx.y;
    int k = blockIdx.y * 32 + ty, n = blockIdx.x * 32 + tx;
    s[ty][tx] = W[(size_t)k * DO + n];
    __syncthreads();
    int on = blockIdx.x * 32 + ty, ok = blockIdx.y * 32 + tx;
    float x = s[tx][ty];
    __nv_bfloat16 h = __float2bfloat16(x);
    __nv_bfloat16 l = __float2bfloat16(x - __bfloat162float(h));
    hi[(size_t)on * K + ok] = h;
    lo[(size_t)on * K + ok] = l;
}

// ---------------- activation hi/lo split ------------------------------------
__global__ void asplit_kernel(const float4* __restrict__ A,
                              __nv_bfloat162* __restrict__ hi, __nv_bfloat162* __restrict__ lo, long n4) {
    long i = (long)blockIdx.x * 256 + threadIdx.x;
    if (i >= n4) return;
    float4 v = A[i];
    __nv_bfloat16 hx = __float2bfloat16(v.x), hy = __float2bfloat16(v.y);
    __nv_bfloat16 hz = __float2bfloat16(v.z), hw = __float2bfloat16(v.w);
    __nv_bfloat16 lx = __float2bfloat16(v.x - __bfloat162float(hx));
    __nv_bfloat16 ly = __float2bfloat16(v.y - __bfloat162float(hy));
    __nv_bfloat16 lz = __float2bfloat16(v.z - __bfloat162float(hz));
    __nv_bfloat16 lw = __float2bfloat16(v.w - __bfloat162float(hw));
    hi[2 * i]     = __nv_bfloat162(hx, hy);
    hi[2 * i + 1] = __nv_bfloat162(hz, hw);
    lo[2 * i]     = __nv_bfloat162(lx, ly);
    lo[2 * i + 1] = __nv_bfloat162(lz, lw);
}

// ---------------- split-bf16 HMMA GEMM --------------------------------------
// C[m,n] = op( sum_k A[m,k]*Wt[n,k] + bias[n] [, Radd] )
// MODE 0: +bias   MODE 1: relu(+bias)   MODE 2: relu(relu(+bias)+Radd)
// BM=128 BN=128 BK=32, 256 thr (8 warps, warp tile 32x64), 3-stage cp.async.
// 3 HMMA products per logical mma: AhiBhi + AhiBlo + AloBhi, fp32 accum.
#define GSTAGES 3
#define ROWB 80          // 32 bf16 = 64B data + 16B pad per smem row
#define PLANE (128 * ROWB)           // 10240 B
#define STAGEB (4 * PLANE)           // 40960 B
#define GEMM_SMEM (GSTAGES * STAGEB) // 122880 B

template <int MODE>
__global__ void __launch_bounds__(256, 1)
hmma_gemm_kernel(const __nv_bfloat16* __restrict__ Ahi, const __nv_bfloat16* __restrict__ Alo,
                 const __nv_bfloat16* __restrict__ Bhi, const __nv_bfloat16* __restrict__ Blo,
                 const float* __restrict__ bias, const float* __restrict__ Radd,
                 float* __restrict__ C, int N, int K, int DO) {
    extern __shared__ char smem[];
    const uint32_t sb = smem_u32(smem);
    const int tid = threadIdx.x;
    const int lane = tid & 31;
    const int wid = tid >> 5;
    const int wm = wid & 3;   // 4 warps along M (32 rows each)
    const int wn = wid >> 2;  // 2 warps along N (64 cols each)
    const int bm = blockIdx.x * 128;
    const int bn = blockIdx.y * 128;
    const int NC = K >> 5;

    float acc[2][8][4];
#pragma unroll
    for (int t = 0; t < 2; t++)
#pragma unroll
        for (int n = 0; n < 8; n++)
#pragma unroll
            for (int q = 0; q < 4; q++) acc[t][n][q] = 0.f;

    // per-thread load slots: 2 x (row, chunk) covering 128x4 16B-chunks
    const int r0s = (tid >> 2), c0s = (tid & 3);              // slot 0: rows 0..63
    const int r1s = r0s + 64, c1s = c0s;                      // slot 1: rows 64..127

    auto load_stage = [&](int chunk, int s) {
        const uint32_t base = sb + s * STAGEB;
        const int k0 = chunk << 5;
#pragma unroll
        for (int j = 0; j < 2; j++) {
            const int r = j ? r1s : r0s;
            const int c = j ? c1s : c0s;
            const uint32_t off = (uint32_t)r * ROWB + (uint32_t)c * 16u;
            const int col = k0 + c * 8;
            long arow = bm + r;
            bool ok = arow < N;
            size_t ao = (size_t)(ok ? arow : 0) * K + col;
            cp16(base + off,             Ahi + ao, ok);
            cp16(base + PLANE + off,     Alo + ao, ok);
            size_t bo = (size_t)(bn + r) * K + col;
            cp16(base + 2 * PLANE + off, Bhi + bo, true);
            cp16(base + 3 * PLANE + off, Blo + bo, true);
        }
    };

    // prologue: prefetch GSTAGES-1 chunks
#pragma unroll
    for (int i = 0; i < GSTAGES - 1; i++) {
        if (i < NC) load_stage(i, i);
        CP_COMMIT();
    }

    // ldmatrix lane addressing (within tile, relative offsets)
    const int a_row = wm * 32 + (lane & 15);                  // + t*16
    const int a_cc  = (lane >> 4);                            // + ks*2
    const int b_row = wn * 64 + ((lane >> 4) << 3) + (lane & 7);  // + g*16
    const int b_cc  = ((lane >> 3) & 1);                      // + ks*2

    for (int i = 0; i < NC; i++) {
        const int pf = i + GSTAGES - 1;
        if (pf < NC) load_stage(pf, pf % GSTAGES);
        CP_COMMIT();
        asm volatile("cp.async.wait_group %0;" :: "n"(GSTAGES - 1));
        __syncthreads();

        const uint32_t sA  = sb + (i % GSTAGES) * STAGEB;
        const uint32_t sAl = sA + PLANE;
        const uint32_t sB  = sA + 2 * PLANE;
        const uint32_t sBl = sA + 3 * PLANE;

#pragma unroll
        for (int ks = 0; ks < 2; ks++) {
            uint32_t ah[2][4], al[2][4];
#pragma unroll
            for (int t = 0; t < 2; t++) {
                uint32_t off = (uint32_t)(a_row + t * 16) * ROWB + (uint32_t)(a_cc + ks * 2) * 16u;
                LDSM4(ah[t][0], ah[t][1], ah[t][2], ah[t][3], sA + off);
                LDSM4(al[t][0], al[t][1], al[t][2], al[t][3], sAl + off);
            }
            uint32_t bh[8][2], bl[8][2];
#pragma unroll
            for (int g = 0; g < 4; g++) {
                uint32_t off = (uint32_t)(b_row + g * 16) * ROWB + (uint32_t)(b_cc + ks * 2) * 16u;
                LDSM4(bh[2 * g][0], bh[2 * g][1], bh[2 * g + 1][0], bh[2 * g + 1][1], sB + off);
                LDSM4(bl[2 * g][0], bl[2 * g][1], bl[2 * g + 1][0], bl[2 * g + 1][1], sBl + off);
            }
#pragma unroll
            for (int t = 0; t < 2; t++)
#pragma unroll
                for (int n = 0; n < 8; n++) {
                    MMA16816(acc[t][n], ah[t], bh[n]);
                    MMA16816(acc[t][n], ah[t], bl[n]);
                    MMA16816(acc[t][n], al[t], bh[n]);
                }
        }
        __syncthreads();
    }

    // epilogue
#pragma unroll
    for (int t = 0; t < 2; t++) {
        const int rbase = bm + wm * 32 + t * 16 + (lane >> 2);
#pragma unroll
        for (int half = 0; half < 2; half++) {
            const long row = rbase + half * 8;
            if (row < N) {
#pragma unroll
                for (int n = 0; n < 8; n++) {
                    const int cb = bn + wn * 64 + n * 8 + (lane & 3) * 2;
                    float2 b2 = *(const float2*)(bias + cb);
                    float vx = acc[t][n][half * 2 + 0] + b2.x;
                    float vy = acc[t][n][half * 2 + 1] + b2.y;
                    if (MODE >= 1) { vx = fmaxf(vx, 0.f); vy = fmaxf(vy, 0.f); }
                    if (MODE == 2) {
                        float2 r2 = *(const float2*)(Radd + row * DO + cb);
                        vx = fmaxf(vx + r2.x, 0.f);
                        vy = fmaxf(vy + r2.y, 0.f);
                    }
                    float2 o; o.x = vx; o.y = vy;
                    *(float2*)(C + row * DO + cb) = o;
                }
            }
        }
    }
}

// ---------------- row LayerNorm ---------------------------------------------
__global__ void ln_kernel(const float* __restrict__ in, const float* __restrict__ gam,
                          const float* __restrict__ bet, float* __restrict__ out, int D) {
    const int row = blockIdx.x;
    const float4* ip = (const float4*)(in + (size_t)row * D);
    float4* op = (float4*)(out + (size_t)row * D);
    const int nv = D >> 2;
    float4 v[4];
    int cnt = 0;
    float s = 0.f, ss = 0.f;
    for (int i = threadIdx.x; i < nv; i += 256) {
        float4 x = ip[i];
        v[cnt++] = x;
        s  += x.x + x.y + x.z + x.w;
        ss += x.x * x.x + x.y * x.y + x.z * x.z + x.w * x.w;
    }
#pragma unroll
    for (int o = 16; o; o >>= 1) {
        s  += __shfl_xor_sync(0xffffffffu, s, o);
        ss += __shfl_xor_sync(0xffffffffu, ss, o);
    }
    __shared__ float rs[8], rss[8], stats[2];
    const int w = threadIdx.x >> 5, l = threadIdx.x & 31;
    if (l == 0) { rs[w] = s; rss[w] = ss; }
    __syncthreads();
    if (threadIdx.x < 32) {
        float a = (threadIdx.x < 8) ? rs[threadIdx.x]  : 0.f;
        float b = (threadIdx.x < 8) ? rss[threadIdx.x] : 0.f;
#pragma unroll
        for (int o = 4; o; o >>= 1) {
            a += __shfl_xor_sync(0xffffffffu, a, o);
            b += __shfl_xor_sync(0xffffffffu, b, o);
        }
        if (threadIdx.x == 0) {
            float mu  = a / (float)D;
            float var = b / (float)D - mu * mu;
            stats[0] = mu;
            stats[1] = rsqrtf(var + 1e-5f);
        }
    }
    __syncthreads();
    const float mu = stats[0], inv = stats[1];
    cnt = 0;
    for (int i = threadIdx.x; i < nv; i += 256) {
        float4 x = v[cnt++];
        float4 g = ((const float4*)gam)[i];
        float4 b = ((const float4*)bet)[i];
        float4 o;
        o.x = (x.x - mu) * inv * g.x + b.x;
        o.y = (x.y - mu) * inv * g.y + b.y;
        o.z = (x.z - mu) * inv * g.z + b.z;
        o.w = (x.w - mu) * inv * g.w + b.w;
        op[i] = o;
    }
}

// ---------------- host orchestration ----------------------------------------
static void launch_asplit(const float* a, __nv_bfloat16* hi, __nv_bfloat16* lo, int d) {
    long n4 = (long)N_NODES * d / 4;
    asplit_kernel<<<(unsigned)((n4 + 255) / 256), 256>>>(
        (const float4*)a, (__nv_bfloat162*)hi, (__nv_bfloat162*)lo, n4);
}

template <int MODE>
static void launch_gemm(const __nv_bfloat16* ahi, const __nv_bfloat16* alo,
                        const __nv_bfloat16* bhi, const __nv_bfloat16* blo,
                        const float* bias, const float* radd, float* c, int K, int DO) {
    dim3 grid((N_NODES + 127) / 128, DO / 128);
    hmma_gemm_kernel<MODE><<<grid, 256, GEMM_SMEM>>>(ahi, alo, bhi, blo, bias, radd, c, N_NODES, K, DO);
}

static void run_block(const float* hin, int d, int dout, const int* ei,
                      const __nv_bfloat16* whi_a, const __nv_bfloat16* wlo_a, const float* ba,
                      const __nv_bfloat16* whi_b, const __nv_bfloat16* wlo_b, const float* bb,
                      const __nv_bfloat16* whi_r, const __nv_bfloat16* wlo_r, const float* rb,
                      const float* lg, const float* lb,
                      float* z, float* t, float* r, float* hout,
                      __nv_bfloat16* a1hi, __nv_bfloat16* a1lo,
                      __nv_bfloat16* a2hi, __nv_bfloat16* a2lo) {
    long n4 = (long)N_NODES * d / 4;
    copy_kernel<<<(unsigned)((n4 + 255) / 256), 256>>>((const float4*)hin, (float4*)z, n4);
    unsigned per = (unsigned)(d / 4);
    unsigned tot = (unsigned)N_EDGES * per;
    scatter_kernel<<<(tot + 255u) / 256u, 256>>>(hin, ei, z, per, d);

    launch_asplit(hin, a2hi, a2lo, d);   // residual path operand
    launch_asplit(z, a1hi, a1lo, d);     // GIN aggregate operand
    launch_gemm<1>(a1hi, a1lo, whi_a, wlo_a, ba, nullptr, t, d, dout);      // t = relu(z@wa+ba)
    launch_gemm<0>(a2hi, a2lo, whi_r, wlo_r, rb, nullptr, r, d, dout);      // r = hin@rw+rb
    launch_asplit(t, a1hi, a1lo, dout);
    launch_gemm<2>(a1hi, a1lo, whi_b, wlo_b, bb, r, z, dout, dout);         // z = relu(relu(t@wb+bb)+r)
    ln_kernel<<<N_NODES, 256>>>(z, lg, lb, hout, dout);
}

extern "C" void kernel_launch(void* const* d_in, const int* in_sizes, int n_in,
                              void* d_out, int out_size) {
    const float* x   = (const float*)d_in[0];
    const int*   ei  = (const int*)d_in[1];
    const float* w1a = (const float*)d_in[2];
    const float* b1a = (const float*)d_in[3];
    const float* w1b = (const float*)d_in[4];
    const float* b1b = (const float*)d_in[5];
    const float* w2a = (const float*)d_in[6];
    const float* b2a = (const float*)d_in[7];
    const float* w2b = (const float*)d_in[8];
    const float* b2b = (const float*)d_in[9];
    const float* w3a = (const float*)d_in[10];
    const float* b3a = (const float*)d_in[11];
    const float* w3b = (const float*)d_in[12];
    const float* b3b = (const float*)d_in[13];
    const float* rp1w = (const float*)d_in[14];
    const float* rp1b = (const float*)d_in[15];
    const float* rp2w = (const float*)d_in[16];
    const float* rp2b = (const float*)d_in[17];
    const float* rp3w = (const float*)d_in[18];
    const float* rp3b = (const float*)d_in[19];
    const float* ln1g = (const float*)d_in[20];
    const float* ln1b = (const float*)d_in[21];
    const float* ln2g = (const float*)d_in[22];
    const float* ln2b = (const float*)d_in[23];
    const float* ln3g = (const float*)d_in[24];
    const float* ln3b = (const float*)d_in[25];
    float* out = (float*)d_out;

    float *z, *t, *r, *h;
    __nv_bfloat16 *a1hi, *a1lo, *a2hi, *a2lo, *whi, *wlo;
    cudaGetSymbolAddress((void**)&z, g_z);
    cudaGetSymbolAddress((void**)&t, g_t);
    cudaGetSymbolAddress((void**)&r, g_r);
    cudaGetSymbolAddress((void**)&h, g_h);
    cudaGetSymbolAddress((void**)&a1hi, g_a1hi);
    cudaGetSymbolAddress((void**)&a1lo, g_a1lo);
    cudaGetSymbolAddress((void**)&a2hi, g_a2hi);
    cudaGetSymbolAddress((void**)&a2lo, g_a2lo);
    cudaGetSymbolAddress((void**)&whi, g_whi);
    cudaGetSymbolAddress((void**)&wlo, g_wlo);

    cudaFuncSetAttribute(hmma_gemm_kernel<0>, cudaFuncAttributeMaxDynamicSharedMemorySize, GEMM_SMEM);
    cudaFuncSetAttribute(hmma_gemm_kernel<1>, cudaFuncAttributeMaxDynamicSharedMemorySize, GEMM_SMEM);
    cudaFuncSetAttribute(hmma_gemm_kernel<2>, cudaFuncAttributeMaxDynamicSharedMemorySize, GEMM_SMEM);

    // weight plane offsets
    const size_t o_w1a = 0;
    const size_t o_w1b = o_w1a + 128 * 256;
    const size_t o_rp1 = o_w1b + 256 * 256;
    const size_t o_w2a = o_rp1 + 128 * 256;
    const size_t o_w2b = o_w2a + 256 * 512;
    const size_t o_rp2 = o_w2b + 512 * 512;
    const size_t o_w3a = o_rp2 + 256 * 512;
    const size_t o_w3b = o_w3a + 512 * 1024;
    const size_t o_rp3 = o_w3b + 1024 * 1024;

    struct WS { const float* w; size_t off; int K, DO; };
    const WS ws[9] = {
        {w1a, o_w1a, 128, 256},  {w1b, o_w1b, 256, 256},   {rp1w, o_rp1, 128, 256},
        {w2a, o_w2a, 256, 512},  {w2b, o_w2b, 512, 512},   {rp2w, o_rp2, 256, 512},
        {w3a, o_w3a, 512, 1024}, {w3b, o_w3b, 1024, 1024}, {rp3w, o_rp3, 512, 1024},
    };
    for (int i = 0; i < 9; i++) {
        dim3 g(ws[i].DO / 32, ws[i].K / 32), b(32, 32);
        wsplit_kernel<<<g, b>>>(ws[i].w, whi + ws[i].off, wlo + ws[i].off, ws[i].K, ws[i].DO);
    }

    // block 1: 128 -> 256
    run_block(x, 128, 256, ei,
              whi + o_w1a, wlo + o_w1a, b1a, whi + o_w1b, wlo + o_w1b, b1b,
              whi + o_rp1, wlo + o_rp1, rp1b, ln1g, ln1b,
              z, t, r, h, a1hi, a1lo, a2hi, a2lo);
    // block 2: 256 -> 512
    run_block(h, 256, 512, ei,
              whi + o_w2a, wlo + o_w2a, b2a, whi + o_w2b, wlo + o_w2b, b2b,
              whi + o_rp2, wlo + o_rp2, rp2b, ln2g, ln2b,
              z, t, r, h, a1hi, a1lo, a2hi, a2lo);
    // block 3: 512 -> 1024 (LN writes d_out)
    run_block(h, 512, 1024, ei,
              whi + o_w3a, wlo + o_w3a, b3a, whi + o_w3b, wlo + o_w3b, b3b,
              whi + o_rp3, wlo + o_rp3, rp3b, ln3g, ln3b,
              z, t, r, out, a1hi, a1lo, a2hi, a2lo);
}

// round 4
// speedup vs baseline: 2.3678x; 1.1987x over previous
#include <cuda_runtime.h>
#include <cuda_bf16.h>
#include <math.h>
#include <stdint.h>

#define N_NODES 50000
#define N_EDGES 800000

// ---------------- scratch (static device arrays; no cudaMalloc) -----------
__device__ float g_z[(size_t)N_NODES * 1024];   // pre-LN buffer
__device__ float g_r[(size_t)N_NODES * 1024];   // residual (fp32)
__device__ float g_h[(size_t)N_NODES * 1024];   // LN output
__device__ __nv_bfloat16 g_a1hi[(size_t)N_NODES * 1024];  // agg split
__device__ __nv_bfloat16 g_a1lo[(size_t)N_NODES * 1024];
__device__ __nv_bfloat16 g_a2hi[(size_t)N_NODES * 1024];  // residual-input split
__device__ __nv_bfloat16 g_a2lo[(size_t)N_NODES * 1024];
__device__ __nv_bfloat16 g_a3hi[(size_t)N_NODES * 1024];  // t split
__device__ __nv_bfloat16 g_a3lo[(size_t)N_NODES * 1024];
#define W_TOTAL 2752512
__device__ __nv_bfloat16 g_whi[W_TOTAL];
__device__ __nv_bfloat16 g_wlo[W_TOTAL];
// CSR scratch
__device__ int g_cnt[N_NODES];
__device__ int g_off[N_NODES];
__device__ int g_cur[N_NODES];
__device__ int g_esrc[N_EDGES];
__device__ int g_bsum[256];

// ============================ PTX helpers ==================================
__device__ __forceinline__ uint32_t smem_u32(const void* p) {
    uint32_t a;
    asm("{ .reg .u64 t; cvta.to.shared.u64 t, %1; cvt.u32.u64 %0, t; }" : "=r"(a) : "l"(p));
    return a;
}
__device__ __forceinline__ void cp16(uint32_t dst, const void* src, bool ok) {
    int sz = ok ? 16 : 0;
    asm volatile("cp.async.cg.shared.global [%0], [%1], 16, %2;" :: "r"(dst), "l"(src), "r"(sz) : "memory");
}
#define CP_COMMIT() asm volatile("cp.async.commit_group;" ::: "memory")

#define LDSM4(r0, r1, r2, r3, addr) \
    asm volatile("ldmatrix.sync.aligned.m8n8.x4.shared.b16 {%0,%1,%2,%3}, [%4];" \
                 : "=r"(r0), "=r"(r1), "=r"(r2), "=r"(r3) : "r"(addr))

#define MMA16816(d, a, b) \
    asm volatile("mma.sync.aligned.m16n8k16.row.col.f32.bf16.bf16.f32 " \
                 "{%0,%1,%2,%3}, {%4,%5,%6,%7}, {%8,%9}, {%0,%1,%2,%3};" \
                 : "+f"((d)[0]), "+f"((d)[1]), "+f"((d)[2]), "+f"((d)[3]) \
                 : "r"((a)[0]), "r"((a)[1]), "r"((a)[2]), "r"((a)[3]), "r"((b)[0]), "r"((b)[1]))

__device__ __forceinline__ __nv_bfloat162 split_hi2(float x, float y, __nv_bfloat162& lo) {
    __nv_bfloat16 hx = __float2bfloat16(x), hy = __float2bfloat16(y);
    lo = __nv_bfloat162(__float2bfloat16(x - __bfloat162float(hx)),
                        __float2bfloat16(y - __bfloat162float(hy)));
    return __nv_bfloat162(hx, hy);
}

// ======================= CSR build =========================================
__global__ void csr_zero(int* cnt, int* cur) {
    int i = blockIdx.x * 256 + threadIdx.x;
    if (i < N_NODES) { cnt[i] = 0; cur[i] = 0; }
}
__global__ void csr_hist(const int* __restrict__ ei, int* cnt) {
    int e = blockIdx.x * 256 + threadIdx.x;
    if (e < N_EDGES) atomicAdd(&cnt[ei[N_EDGES + e]], 1);
}
__global__ void csr_scan1(const int* __restrict__ cnt, int* off, int* bsum) {
    __shared__ int s[256];
    int i = blockIdx.x * 256 + threadIdx.x;
    int v = (i < N_NODES) ? cnt[i] : 0;
    s[threadIdx.x] = v;
    __syncthreads();
#pragma unroll
    for (int d = 1; d < 256; d <<= 1) {
        int t = (threadIdx.x >= d) ? s[threadIdx.x - d] : 0;
        __syncthreads();
        s[threadIdx.x] += t;
        __syncthreads();
    }
    if (i < N_NODES) off[i] = s[threadIdx.x] - v;
    if (threadIdx.x == 255) bsum[blockIdx.x] = s[255];
}
__global__ void csr_scan2(int* bsum, int nb) {
    __shared__ int s[256];
    int v = (threadIdx.x < nb) ? bsum[threadIdx.x] : 0;
    s[threadIdx.x] = v;
    __syncthreads();
#pragma unroll
    for (int d = 1; d < 256; d <<= 1) {
        int t = (threadIdx.x >= d) ? s[threadIdx.x - d] : 0;
        __syncthreads();
        s[threadIdx.x] += t;
        __syncthreads();
    }
    if (threadIdx.x < nb) bsum[threadIdx.x] = s[threadIdx.x] - v;
}
__global__ void csr_scan3(int* off, const int* __restrict__ bsum) {
    int i = blockIdx.x * 256 + threadIdx.x;
    if (i < N_NODES) off[i] += bsum[blockIdx.x];
}
__global__ void csr_fill(const int* __restrict__ ei, const int* __restrict__ off,
                         int* cur, int* esrc) {
    int e = blockIdx.x * 256 + threadIdx.x;
    if (e >= N_EDGES) return;
    int d = ei[N_EDGES + e];
    int p = off[d] + atomicAdd(&cur[d], 1);
    esrc[p] = ei[e];
}

// ================= aggregation: z = h[n] + sum_{src->n} h[src] =============
// writes split bf16 planes directly (no fp32 z, no atomics)
template <int D>
__global__ void __launch_bounds__(128)
aggregate_kernel(const float* __restrict__ h, const int* __restrict__ off,
                 const int* __restrict__ cnt, const int* __restrict__ esrc,
                 __nv_bfloat162* __restrict__ hi, __nv_bfloat162* __restrict__ lo) {
    constexpr int TPN = D / 4;          // threads per node
    constexpr int NPB = 128 / TPN;      // nodes per block
    const int node = blockIdx.x * NPB + threadIdx.x / TPN;
    if (node >= N_NODES) return;
    const int t = threadIdx.x % TPN;
    const float4* hp = (const float4*)h;

    float4 acc = hp[(size_t)node * TPN + t];
    const int s = off[node];
    const int e = s + cnt[node];
    int i = s;
#pragma unroll 1
    for (; i + 4 <= e; i += 4) {
        int s0 = esrc[i], s1 = esrc[i + 1], s2 = esrc[i + 2], s3 = esrc[i + 3];
        float4 v0 = hp[(size_t)s0 * TPN + t];
        float4 v1 = hp[(size_t)s1 * TPN + t];
        float4 v2 = hp[(size_t)s2 * TPN + t];
        float4 v3 = hp[(size_t)s3 * TPN + t];
        acc.x += v0.x + v1.x + v2.x + v3.x;
        acc.y += v0.y + v1.y + v2.y + v3.y;
        acc.z += v0.z + v1.z + v2.z + v3.z;
        acc.w += v0.w + v1.w + v2.w + v3.w;
    }
    for (; i < e; i++) {
        float4 v = hp[(size_t)esrc[i] * TPN + t];
        acc.x += v.x; acc.y += v.y; acc.z += v.z; acc.w += v.w;
    }
    __nv_bfloat162 l0, l1;
    __nv_bfloat162 h0 = split_hi2(acc.x, acc.y, l0);
    __nv_bfloat162 h1 = split_hi2(acc.z, acc.w, l1);
    size_t o = (size_t)node * (D / 2) + t * 2;
    hi[o] = h0; hi[o + 1] = h1;
    lo[o] = l0; lo[o + 1] = l1;
}

// ---------------- activation hi/lo split (only for x) -----------------------
__global__ void asplit_kernel(const float4* __restrict__ A,
                              __nv_bfloat162* __restrict__ hi, __nv_bfloat162* __restrict__ lo, long n4) {
    long i = (long)blockIdx.x * 256 + threadIdx.x;
    if (i >= n4) return;
    float4 v = A[i];
    __nv_bfloat162 l0, l1;
    __nv_bfloat162 h0 = split_hi2(v.x, v.y, l0);
    __nv_bfloat162 h1 = split_hi2(v.z, v.w, l1);
    hi[2 * i] = h0; hi[2 * i + 1] = h1;
    lo[2 * i] = l0; lo[2 * i + 1] = l1;
}

// ---------------- weight transpose + hi/lo split ----------------------------
__global__ void wsplit_kernel(const float* __restrict__ W,
                              __nv_bfloat16* __restrict__ hi, __nv_bfloat16* __restrict__ lo,
                              int K, int DO) {
    __shared__ float s[32][33];
    int tx = threadIdx.x, ty = threadIdx.y;
    int k = blockIdx.y * 32 + ty, n = blockIdx.x * 32 + tx;
    s[ty][tx] = W[(size_t)k * DO + n];
    __syncthreads();
    int on = blockIdx.x * 32 + ty, ok = blockIdx.y * 32 + tx;
    float x = s[tx][ty];
    __nv_bfloat16 h = __float2bfloat16(x);
    __nv_bfloat16 l = __float2bfloat16(x - __bfloat162float(h));
    hi[(size_t)on * K + ok] = h;
    lo[(size_t)on * K + ok] = l;
}

// ---------------- split-bf16 HMMA GEMM --------------------------------------
// MODE 0: C = A@Wt + bias (fp32)
// MODE 1: relu(A@Wt + bias) -> split bf16 planes Chi/Clo
// MODE 2: C = relu( relu(A@Wt+bias) + Radd ) (fp32)
#define GSTAGES 3
#define ROWB 80
#define PLANE (128 * ROWB)
#define STAGEB (4 * PLANE)
#define GEMM_SMEM (GSTAGES * STAGEB)

template <int MODE>
__global__ void __launch_bounds__(256, 1)
hmma_gemm_kernel(const __nv_bfloat16* __restrict__ Ahi, const __nv_bfloat16* __restrict__ Alo,
                 const __nv_bfloat16* __restrict__ Bhi, const __nv_bfloat16* __restrict__ Blo,
                 const float* __restrict__ bias, const float* __restrict__ Radd,
                 float* __restrict__ C,
                 __nv_bfloat162* __restrict__ Chi, __nv_bfloat162* __restrict__ Clo,
                 int N, int K, int DO) {
    extern __shared__ char smem[];
    const uint32_t sb = smem_u32(smem);
    const int tid = threadIdx.x;
    const int lane = tid & 31;
    const int wid = tid >> 5;
    const int wm = wid & 3;
    const int wn = wid >> 2;
    const int bm = blockIdx.x * 128;
    const int bn = blockIdx.y * 128;
    const int NC = K >> 5;

    float acc[2][8][4];
#pragma unroll
    for (int t = 0; t < 2; t++)
#pragma unroll
        for (int n = 0; n < 8; n++)
#pragma unroll
            for (int q = 0; q < 4; q++) acc[t][n][q] = 0.f;

    const int r0s = (tid >> 2), c0s = (tid & 3);
    const int r1s = r0s + 64, c1s = c0s;

    auto load_stage = [&](int chunk, int s) {
        const uint32_t base = sb + s * STAGEB;
        const int k0 = chunk << 5;
#pragma unroll
        for (int j = 0; j < 2; j++) {
            const int r = j ? r1s : r0s;
            const int c = j ? c1s : c0s;
            const uint32_t off = (uint32_t)r * ROWB + (uint32_t)c * 16u;
            const int col = k0 + c * 8;
            long arow = bm + r;
            bool ok = arow < N;
            size_t ao = (size_t)(ok ? arow : 0) * K + col;
            cp16(base + off,             Ahi + ao, ok);
            cp16(base + PLANE + off,     Alo + ao, ok);
            size_t bo = (size_t)(bn + r) * K + col;
            cp16(base + 2 * PLANE + off, Bhi + bo, true);
            cp16(base + 3 * PLANE + off, Blo + bo, true);
        }
    };

#pragma unroll
    for (int i = 0; i < GSTAGES - 1; i++) {
        if (i < NC) load_stage(i, i);
        CP_COMMIT();
    }

    const int a_row = wm * 32 + (lane & 15);
    const int a_cc  = (lane >> 4);
    const int b_row = wn * 64 + ((lane >> 4) << 3) + (lane & 7);
    const int b_cc  = ((lane >> 3) & 1);

    for (int i = 0; i < NC; i++) {
        const int pf = i + GSTAGES - 1;
        if (pf < NC) load_stage(pf, pf % GSTAGES);
        CP_COMMIT();
        asm volatile("cp.async.wait_group %0;" :: "n"(GSTAGES - 1));
        __syncthreads();

        const uint32_t sA  = sb + (i % GSTAGES) * STAGEB;
        const uint32_t sAl = sA + PLANE;
        const uint32_t sB  = sA + 2 * PLANE;
        const uint32_t sBl = sA + 3 * PLANE;

#pragma unroll
        for (int ks = 0; ks < 2; ks++) {
            uint32_t ah[2][4], al[2][4];
#pragma unroll
            for (int t = 0; t < 2; t++) {
                uint32_t off = (uint32_t)(a_row + t * 16) * ROWB + (uint32_t)(a_cc + ks * 2) * 16u;
                LDSM4(ah[t][0], ah[t][1], ah[t][2], ah[t][3], sA + off);
                LDSM4(al[t][0], al[t][1], al[t][2], al[t][3], sAl + off);
            }
            uint32_t bh[8][2], bl[8][2];
#pragma unroll
            for (int g = 0; g < 4; g++) {
                uint32_t off = (uint32_t)(b_row + g * 16) * ROWB + (uint32_t)(b_cc + ks * 2) * 16u;
                LDSM4(bh[2 * g][0], bh[2 * g][1], bh[2 * g + 1][0], bh[2 * g + 1][1], sB + off);
                LDSM4(bl[2 * g][0], bl[2 * g][1], bl[2 * g + 1][0], bl[2 * g + 1][1], sBl + off);
            }
#pragma unroll
            for (int t = 0; t < 2; t++)
#pragma unroll
                for (int n = 0; n < 8; n++) {
                    MMA16816(acc[t][n], ah[t], bh[n]);
                    MMA16816(acc[t][n], ah[t], bl[n]);
                    MMA16816(acc[t][n], al[t], bh[n]);
                }
        }
        __syncthreads();
    }

    // epilogue
#pragma unroll
    for (int t = 0; t < 2; t++) {
        const int rbase = bm + wm * 32 + t * 16 + (lane >> 2);
#pragma unroll
        for (int half = 0; half < 2; half++) {
            const long row = rbase + half * 8;
            if (row < N) {
#pragma unroll
                for (int n = 0; n < 8; n++) {
                    const int cb = bn + wn * 64 + n * 8 + (lane & 3) * 2;
                    float2 b2 = *(const float2*)(bias + cb);
                    float vx = acc[t][n][half * 2 + 0] + b2.x;
                    float vy = acc[t][n][half * 2 + 1] + b2.y;
                    if (MODE >= 1) { vx = fmaxf(vx, 0.f); vy = fmaxf(vy, 0.f); }
                    if (MODE == 2) {
                        float2 r2 = *(const float2*)(Radd + row * DO + cb);
                        vx = fmaxf(vx + r2.x, 0.f);
                        vy = fmaxf(vy + r2.y, 0.f);
                    }
                    if (MODE == 1) {
                        __nv_bfloat162 lo2;
                        __nv_bfloat162 hi2 = split_hi2(vx, vy, lo2);
                        size_t o = ((size_t)row * DO + cb) >> 1;
                        Chi[o] = hi2;
                        Clo[o] = lo2;
                    } else {
                        float2 o; o.x = vx; o.y = vy;
                        *(float2*)(C + row * DO + cb) = o;
                    }
                }
            }
        }
    }
}

// ---------------- row LayerNorm (optionally emits split planes) -------------
__global__ void ln_kernel(const float* __restrict__ in, const float* __restrict__ gam,
                          const float* __restrict__ bet, float* __restrict__ out,
                          __nv_bfloat162* __restrict__ ohi, __nv_bfloat162* __restrict__ olo,
                          int D) {
    const int row = blockIdx.x;
    const float4* ip = (const float4*)(in + (size_t)row * D);
    float4* op = (float4*)(out + (size_t)row * D);
    const int nv = D >> 2;
    float4 v[4];
    int cnt = 0;
    float s = 0.f, ss = 0.f;
    for (int i = threadIdx.x; i < nv; i += 256) {
        float4 x = ip[i];
        v[cnt++] = x;
        s  += x.x + x.y + x.z + x.w;
        ss += x.x * x.x + x.y * x.y + x.z * x.z + x.w * x.w;
    }
#pragma unroll
    for (int o = 16; o; o >>= 1) {
        s  += __shfl_xor_sync(0xffffffffu, s, o);
        ss += __shfl_xor_sync(0xffffffffu, ss, o);
    }
    __shared__ float rs[8], rss[8], stats[2];
    const int w = threadIdx.x >> 5, l = threadIdx.x & 31;
    if (l == 0) { rs[w] = s; rss[w] = ss; }
    __syncthreads();
    if (threadIdx.x < 32) {
        float a = (threadIdx.x < 8) ? rs[threadIdx.x]  : 0.f;
        float b = (threadIdx.x < 8) ? rss[threadIdx.x] : 0.f;
#pragma unroll
        for (int o = 4; o; o >>= 1) {
            a += __shfl_xor_sync(0xffffffffu, a, o);
            b += __shfl_xor_sync(0xffffffffu, b, o);
        }
        if (threadIdx.x == 0) {
            float mu  = a / (float)D;
            float var = b / (float)D - mu * mu;
            stats[0] = mu;
            stats[1] = rsqrtf(var + 1e-5f);
        }
    }
    __syncthreads();
    const float mu = stats[0], inv = stats[1];
    cnt = 0;
    for (int i = threadIdx.x; i < nv; i += 256) {
        float4 x = v[cnt++];
        float4 g = ((const float4*)gam)[i];
        float4 b = ((const float4*)bet)[i];
        float4 o;
        o.x = (x.x - mu) * inv * g.x + b.x;
        o.y = (x.y - mu) * inv * g.y + b.y;
        o.z = (x.z - mu) * inv * g.z + b.z;
        o.w = (x.w - mu) * inv * g.w + b.w;
        op[i] = o;
        if (ohi) {
            __nv_bfloat162 l0, l1;
            __nv_bfloat162 h0 = split_hi2(o.x, o.y, l0);
            __nv_bfloat162 h1 = split_hi2(o.z, o.w, l1);
            size_t base = (size_t)row * (D >> 1) + i * 2;
            ohi[base] = h0; ohi[base + 1] = h1;
            olo[base] = l0; olo[base + 1] = l1;
        }
    }
}

// ---------------- host orchestration ----------------------------------------
template <int MODE>
static void launch_gemm(const __nv_bfloat16* ahi, const __nv_bfloat16* alo,
                        const __nv_bfloat16* bhi, const __nv_bfloat16* blo,
                        const float* bias, const float* radd, float* c,
                        __nv_bfloat16* chi, __nv_bfloat16* clo, int K, int DO) {
    dim3 grid((N_NODES + 127) / 128, DO / 128);
    hmma_gemm_kernel<MODE><<<grid, 256, GEMM_SMEM>>>(
        ahi, alo, bhi, blo, bias, radd, c,
        (__nv_bfloat162*)chi, (__nv_bfloat162*)clo, N_NODES, K, DO);
}

extern "C" void kernel_launch(void* const* d_in, const int* in_sizes, int n_in,
                              void* d_out, int out_size) {
    const float* x   = (const float*)d_in[0];
    const int*   ei  = (const int*)d_in[1];
    const float* w1a = (const float*)d_in[2];
    const float* b1a = (const float*)d_in[3];
    const float* w1b = (const float*)d_in[4];
    const float* b1b = (const float*)d_in[5];
    const float* w2a = (const float*)d_in[6];
    const float* b2a = (const float*)d_in[7];
    const float* w2b = (const float*)d_in[8];
    const float* b2b = (const float*)d_in[9];
    const float* w3a = (const float*)d_in[10];
    const float* b3a = (const float*)d_in[11];
    const float* w3b = (const float*)d_in[12];
    const float* b3b = (const float*)d_in[13];
    const float* rp1w = (const float*)d_in[14];
    const float* rp1b = (const float*)d_in[15];
    const float* rp2w = (const float*)d_in[16];
    const float* rp2b = (const float*)d_in[17];
    const float* rp3w = (const float*)d_in[18];
    const float* rp3b = (const float*)d_in[19];
    const float* ln1g = (const float*)d_in[20];
    const float* ln1b = (const float*)d_in[21];
    const float* ln2g = (const float*)d_in[22];
    const float* ln2b = (const float*)d_in[23];
    const float* ln3g = (const float*)d_in[24];
    const float* ln3b = (const float*)d_in[25];
    float* out = (float*)d_out;

    float *z, *r, *h;
    __nv_bfloat16 *a1hi, *a1lo, *a2hi, *a2lo, *a3hi, *a3lo, *whi, *wlo;
    int *csr_cnt, *csr_off, *csr_cur, *esrc, *bsum;
    cudaGetSymbolAddress((void**)&z, g_z);
    cudaGetSymbolAddress((void**)&r, g_r);
    cudaGetSymbolAddress((void**)&h, g_h);
    cudaGetSymbolAddress((void**)&a1hi, g_a1hi);
    cudaGetSymbolAddress((void**)&a1lo, g_a1lo);
    cudaGetSymbolAddress((void**)&a2hi, g_a2hi);
    cudaGetSymbolAddress((void**)&a2lo, g_a2lo);
    cudaGetSymbolAddress((void**)&a3hi, g_a3hi);
    cudaGetSymbolAddress((void**)&a3lo, g_a3lo);
    cudaGetSymbolAddress((void**)&whi, g_whi);
    cudaGetSymbolAddress((void**)&wlo, g_wlo);
    cudaGetSymbolAddress((void**)&csr_cnt, g_cnt);
    cudaGetSymbolAddress((void**)&csr_off, g_off);
    cudaGetSymbolAddress((void**)&csr_cur, g_cur);
    cudaGetSymbolAddress((void**)&esrc, g_esrc);
    cudaGetSymbolAddress((void**)&bsum, g_bsum);

    cudaFuncSetAttribute(hmma_gemm_kernel<0>, cudaFuncAttributeMaxDynamicSharedMemorySize, GEMM_SMEM);
    cudaFuncSetAttribute(hmma_gemm_kernel<1>, cudaFuncAttributeMaxDynamicSharedMemorySize, GEMM_SMEM);
    cudaFuncSetAttribute(hmma_gemm_kernel<2>, cudaFuncAttributeMaxDynamicSharedMemorySize, GEMM_SMEM);

    // ---- CSR build (once per call) ----
    const int NB = (N_NODES + 255) / 256;   // 196
    const int EB = (N_EDGES + 255) / 256;
    csr_zero<<<NB, 256>>>(csr_cnt, csr_cur);
    csr_hist<<<EB, 256>>>(ei, csr_cnt);
    csr_scan1<<<NB, 256>>>(csr_cnt, csr_off, bsum);
    csr_scan2<<<1, 256>>>(bsum, NB);
    csr_scan3<<<NB, 256>>>(csr_off, bsum);
    csr_fill<<<EB, 256>>>(ei, csr_off, csr_cur, esrc);

    // ---- weight split (once per call) ----
    const size_t o_w1a = 0;
    const size_t o_w1b = o_w1a + 128 * 256;
    const size_t o_rp1 = o_w1b + 256 * 256;
    const size_t o_w2a = o_rp1 + 128 * 256;
    const size_t o_w2b = o_w2a + 256 * 512;
    const size_t o_rp2 = o_w2b + 512 * 512;
    const size_t o_w3a = o_rp2 + 256 * 512;
    const size_t o_w3b = o_w3a + 512 * 1024;
    const size_t o_rp3 = o_w3b + 1024 * 1024;

    struct WS { const float* w; size_t off; int K, DO; };
    const WS ws[9] = {
        {w1a, o_w1a, 128, 256},  {w1b, o_w1b, 256, 256},   {rp1w, o_rp1, 128, 256},
        {w2a, o_w2a, 256, 512},  {w2b, o_w2b, 512, 512},   {rp2w, o_rp2, 256, 512},
        {w3a, o_w3a, 512, 1024}, {w3b, o_w3b, 1024, 1024}, {rp3w, o_rp3, 512, 1024},
    };
    for (int i = 0; i < 9; i++) {
        dim3 g(ws[i].DO / 32, ws[i].K / 32), b(32, 32);
        wsplit_kernel<<<g, b>>>(ws[i].w, whi + ws[i].off, wlo + ws[i].off, ws[i].K, ws[i].DO);
    }

    // residual input split for block 1 (x)
    {
        long n4 = (long)N_NODES * 128 / 4;
        asplit_kernel<<<(unsigned)((n4 + 255) / 256), 256>>>(
            (const float4*)x, (__nv_bfloat162*)a2hi, (__nv_bfloat162*)a2lo, n4);
    }

    // ---- block 1: 128 -> 256 ----
    aggregate_kernel<128><<<(N_NODES + 3) / 4, 128>>>(x, csr_off, csr_cnt, esrc,
                                                      (__nv_bfloat162*)a1hi, (__nv_bfloat162*)a1lo);
    launch_gemm<1>(a1hi, a1lo, whi + o_w1a, wlo + o_w1a, b1a, nullptr, nullptr, a3hi, a3lo, 128, 256);
    launch_gemm<0>(a2hi, a2lo, whi + o_rp1, wlo + o_rp1, rp1b, nullptr, r, nullptr, nullptr, 128, 256);
    launch_gemm<2>(a3hi, a3lo, whi + o_w1b, wlo + o_w1b, b1b, r, z, nullptr, nullptr, 256, 256);
    ln_kernel<<<N_NODES, 256>>>(z, ln1g, ln1b, h, (__nv_bfloat162*)a2hi, (__nv_bfloat162*)a2lo, 256);

    // ---- block 2: 256 -> 512 ----
    aggregate_kernel<256><<<(N_NODES + 1) / 2, 128>>>(h, csr_off, csr_cnt, esrc,
                                                      (__nv_bfloat162*)a1hi, (__nv_bfloat162*)a1lo);
    launch_gemm<1>(a1hi, a1lo, whi + o_w2a, wlo + o_w2a, b2a, nullptr, nullptr, a3hi, a3lo, 256, 512);
    launch_gemm<0>(a2hi, a2lo, whi + o_rp2, wlo + o_rp2, rp2b, nullptr, r, nullptr, nullptr, 256, 512);
    launch_gemm<2>(a3hi, a3lo, whi + o_w2b, wlo + o_w2b, b2b, r, z, nullptr, nullptr, 512, 512);
    ln_kernel<<<N_NODES, 256>>>(z, ln2g, ln2b, h, (__nv_bfloat162*)a2hi, (__nv_bfloat162*)a2lo, 512);

    // ---- block 3: 512 -> 1024 ----
    aggregate_kernel<512><<<N_NODES, 128>>>(h, csr_off, csr_cnt, esrc,
                                            (__nv_bfloat162*)a1hi, (__nv_bfloat162*)a1lo);
    launch_gemm<1>(a1hi, a1lo, whi + o_w3a, wlo + o_w3a, b3a, nullptr, nullptr, a3hi, a3lo, 512, 1024);
    launch_gemm<0>(a2hi, a2lo, whi + o_rp3, wlo + o_rp3, rp3b, nullptr, r, nullptr, nullptr, 512, 1024);
    launch_gemm<2>(a3hi, a3lo, whi + o_w3b, wlo + o_w3b, b3b, r, z, nullptr, nullptr, 1024, 1024);
    ln_kernel<<<N_NODES, 256>>>(z, ln3g, ln3b, out, nullptr, nullptr, 1024);
}

// round 5
// speedup vs baseline: 2.5666x; 1.0839x over previous
#include <cuda_runtime.h>
#include <cuda_bf16.h>
#include <math.h>
#include <stdint.h>

#define N_NODES 50000
#define N_EDGES 800000

// ---------------- scratch (static device arrays; no cudaMalloc) -----------
__device__ float g_z[(size_t)N_NODES * 1024];   // pre-LN buffer
__device__ float g_r[(size_t)N_NODES * 1024];   // residual (fp32)
__device__ float g_h[(size_t)N_NODES * 1024];   // LN output
__device__ __nv_bfloat16 g_a1hi[(size_t)N_NODES * 1024];  // agg split
__device__ __nv_bfloat16 g_a1lo[(size_t)N_NODES * 1024];
__device__ __nv_bfloat16 g_a2hi[(size_t)N_NODES * 1024];  // residual-input split
__device__ __nv_bfloat16 g_a2lo[(size_t)N_NODES * 1024];
__device__ __nv_bfloat16 g_a3hi[(size_t)N_NODES * 1024];  // t split
__device__ __nv_bfloat16 g_a3lo[(size_t)N_NODES * 1024];
#define W_TOTAL 2752512
__device__ __nv_bfloat16 g_whi[W_TOTAL];
__device__ __nv_bfloat16 g_wlo[W_TOTAL];
// CSR scratch
__device__ int g_cnt[N_NODES];
__device__ int g_off[N_NODES];
__device__ int g_cur[N_NODES];
__device__ int g_esrc[N_EDGES];
__device__ int g_bsum[256];

// ============================ PTX helpers ==================================
__device__ __forceinline__ uint32_t smem_u32(const void* p) {
    uint32_t a;
    asm("{ .reg .u64 t; cvta.to.shared.u64 t, %1; cvt.u32.u64 %0, t; }" : "=r"(a) : "l"(p));
    return a;
}
__device__ __forceinline__ void cp16(uint32_t dst, const void* src, bool ok) {
    int sz = ok ? 16 : 0;
    asm volatile("cp.async.cg.shared.global [%0], [%1], 16, %2;" :: "r"(dst), "l"(src), "r"(sz) : "memory");
}
#define CP_COMMIT() asm volatile("cp.async.commit_group;" ::: "memory")

#define LDSM4(r0, r1, r2, r3, addr) \
    asm volatile("ldmatrix.sync.aligned.m8n8.x4.shared.b16 {%0,%1,%2,%3}, [%4];" \
                 : "=r"(r0), "=r"(r1), "=r"(r2), "=r"(r3) : "r"(addr))

#define MMA16816(d, a, b) \
    asm volatile("mma.sync.aligned.m16n8k16.row.col.f32.bf16.bf16.f32 " \
                 "{%0,%1,%2,%3}, {%4,%5,%6,%7}, {%8,%9}, {%0,%1,%2,%3};" \
                 : "+f"((d)[0]), "+f"((d)[1]), "+f"((d)[2]), "+f"((d)[3]) \
                 : "r"((a)[0]), "r"((a)[1]), "r"((a)[2]), "r"((a)[3]), "r"((b)[0]), "r"((b)[1]))

__device__ __forceinline__ __nv_bfloat162 split_hi2(float x, float y, __nv_bfloat162& lo) {
    __nv_bfloat16 hx = __float2bfloat16(x), hy = __float2bfloat16(y);
    lo = __nv_bfloat162(__float2bfloat16(x - __bfloat162float(hx)),
                        __float2bfloat16(y - __bfloat162float(hy)));
    return __nv_bfloat162(hx, hy);
}

// ======================= CSR build =========================================
__global__ void csr_zero(int* cnt, int* cur) {
    int i = blockIdx.x * 256 + threadIdx.x;
    if (i < N_NODES) { cnt[i] = 0; cur[i] = 0; }
}
__global__ void csr_hist(const int* __restrict__ ei, int* cnt) {
    int e = blockIdx.x * 256 + threadIdx.x;
    if (e < N_EDGES) atomicAdd(&cnt[ei[N_EDGES + e]], 1);
}
__global__ void csr_scan1(const int* __restrict__ cnt, int* off, int* bsum) {
    __shared__ int s[256];
    int i = blockIdx.x * 256 + threadIdx.x;
    int v = (i < N_NODES) ? cnt[i] : 0;
    s[threadIdx.x] = v;
    __syncthreads();
#pragma unroll
    for (int d = 1; d < 256; d <<= 1) {
        int t = (threadIdx.x >= d) ? s[threadIdx.x - d] : 0;
        __syncthreads();
        s[threadIdx.x] += t;
        __syncthreads();
    }
    if (i < N_NODES) off[i] = s[threadIdx.x] - v;
    if (threadIdx.x == 255) bsum[blockIdx.x] = s[255];
}
__global__ void csr_scan2(int* bsum, int nb) {
    __shared__ int s[256];
    int v = (threadIdx.x < nb) ? bsum[threadIdx.x] : 0;
    s[threadIdx.x] = v;
    __syncthreads();
#pragma unroll
    for (int d = 1; d < 256; d <<= 1) {
        int t = (threadIdx.x >= d) ? s[threadIdx.x - d] : 0;
        __syncthreads();
        s[threadIdx.x] += t;
        __syncthreads();
    }
    if (threadIdx.x < nb) bsum[threadIdx.x] = s[threadIdx.x] - v;
}
__global__ void csr_scan3(int* off, const int* __restrict__ bsum) {
    int i = blockIdx.x * 256 + threadIdx.x;
    if (i < N_NODES) off[i] += bsum[blockIdx.x];
}
__global__ void csr_fill(const int* __restrict__ ei, const int* __restrict__ off,
                         int* cur, int* esrc) {
    int e = blockIdx.x * 256 + threadIdx.x;
    if (e >= N_EDGES) return;
    int d = ei[N_EDGES + e];
    int p = off[d] + atomicAdd(&cur[d], 1);
    esrc[p] = ei[e];
}

// ================= aggregation: z = h[n] + sum_{src->n} h[src] =============
template <int D>
__global__ void __launch_bounds__(128)
aggregate_kernel(const float* __restrict__ h, const int* __restrict__ off,
                 const int* __restrict__ cnt, const int* __restrict__ esrc,
                 __nv_bfloat162* __restrict__ hi, __nv_bfloat162* __restrict__ lo) {
    constexpr int TPN = D / 4;
    constexpr int NPB = 128 / TPN;
    const int node = blockIdx.x * NPB + threadIdx.x / TPN;
    if (node >= N_NODES) return;
    const int t = threadIdx.x % TPN;
    const float4* hp = (const float4*)h;

    float4 acc = hp[(size_t)node * TPN + t];
    const int s = off[node];
    const int e = s + cnt[node];
    int i = s;
#pragma unroll 1
    for (; i + 4 <= e; i += 4) {
        int s0 = esrc[i], s1 = esrc[i + 1], s2 = esrc[i + 2], s3 = esrc[i + 3];
        float4 v0 = hp[(size_t)s0 * TPN + t];
        float4 v1 = hp[(size_t)s1 * TPN + t];
        float4 v2 = hp[(size_t)s2 * TPN + t];
        float4 v3 = hp[(size_t)s3 * TPN + t];
        acc.x += v0.x + v1.x + v2.x + v3.x;
        acc.y += v0.y + v1.y + v2.y + v3.y;
        acc.z += v0.z + v1.z + v2.z + v3.z;
        acc.w += v0.w + v1.w + v2.w + v3.w;
    }
    for (; i < e; i++) {
        float4 v = hp[(size_t)esrc[i] * TPN + t];
        acc.x += v.x; acc.y += v.y; acc.z += v.z; acc.w += v.w;
    }
    __nv_bfloat162 l0, l1;
    __nv_bfloat162 h0 = split_hi2(acc.x, acc.y, l0);
    __nv_bfloat162 h1 = split_hi2(acc.z, acc.w, l1);
    size_t o = (size_t)node * (D / 2) + t * 2;
    hi[o] = h0; hi[o + 1] = h1;
    lo[o] = l0; lo[o + 1] = l1;
}

// ---------------- activation hi/lo split (only for x) -----------------------
__global__ void asplit_kernel(const float4* __restrict__ A,
                              __nv_bfloat162* __restrict__ hi, __nv_bfloat162* __restrict__ lo, long n4) {
    long i = (long)blockIdx.x * 256 + threadIdx.x;
    if (i >= n4) return;
    float4 v = A[i];
    __nv_bfloat162 l0, l1;
    __nv_bfloat162 h0 = split_hi2(v.x, v.y, l0);
    __nv_bfloat162 h1 = split_hi2(v.z, v.w, l1);
    hi[2 * i] = h0; hi[2 * i + 1] = h1;
    lo[2 * i] = l0; lo[2 * i + 1] = l1;
}

// ---------------- weight transpose + hi/lo split ----------------------------
__global__ void wsplit_kernel(const float* __restrict__ W,
                              __nv_bfloat16* __restrict__ hi, __nv_bfloat16* __restrict__ lo,
                              int K, int DO) {
    __shared__ float s[32][33];
    int tx = threadIdx.x, ty = threadIdx.y;
    int k = blockIdx.y * 32 + ty, n = blockIdx.x * 32 + tx;
    s[ty][tx] = W[(size_t)k * DO + n];
    __syncthreads();
    int on = blockIdx.x * 32 + ty, ok = blockIdx.y * 32 + tx;
    float x = s[tx][ty];
    __nv_bfloat16 h = __float2bfloat16(x);
    __nv_bfloat16 l = __float2bfloat16(x - __bfloat162float(h));
    hi[(size_t)on * K + ok] = h;
    lo[(size_t)on * K + ok] = l;
}

// ---------------- split-bf16 HMMA GEMM, BM=128 BN=256 BK=32 ------------------
// MODE 0: C = A@Wt + bias (fp32)
// MODE 1: relu(A@Wt + bias) -> split bf16 planes Chi/Clo
// MODE 2: C = relu( relu(A@Wt+bias) + Radd ) (fp32)
// 256 thr (8 warps, warp tile 32x128), 2-stage cp.async.
#define GSTAGES 2
#define ROWB 80
#define A_PLANE (128 * ROWB)            // 10240
#define B_PLANE (256 * ROWB)            // 20480
#define STAGEB (2 * A_PLANE + 2 * B_PLANE)  // 61440
#define GEMM_SMEM (GSTAGES * STAGEB)        // 122880

template <int MODE>
__global__ void __launch_bounds__(256, 1)
hmma_gemm_kernel(const __nv_bfloat16* __restrict__ Ahi, const __nv_bfloat16* __restrict__ Alo,
                 const __nv_bfloat16* __restrict__ Bhi, const __nv_bfloat16* __restrict__ Blo,
                 const float* __restrict__ bias, const float* __restrict__ Radd,
                 float* __restrict__ C,
                 __nv_bfloat162* __restrict__ Chi, __nv_bfloat162* __restrict__ Clo,
                 int N, int K, int DO) {
    extern __shared__ char smem[];
    const uint32_t sb = smem_u32(smem);
    const int tid = threadIdx.x;
    const int lane = tid & 31;
    const int wid = tid >> 5;
    const int wm = wid & 3;          // 4 warps along M (32 rows)
    const int wn = wid >> 2;         // 2 warps along N (128 cols)
    const int bm = blockIdx.x * 128;
    const int bn = blockIdx.y * 256;
    const int NC = K >> 5;

    float acc[2][16][4];
#pragma unroll
    for (int t = 0; t < 2; t++)
#pragma unroll
        for (int n = 0; n < 16; n++)
#pragma unroll
            for (int q = 0; q < 4; q++) acc[t][n][q] = 0.f;

    auto load_stage = [&](int chunk, int s) {
        const uint32_t base = sb + s * STAGEB;
        const int k0 = chunk << 5;
        // A planes: 512 16B-chunks per plane, 2 per thread per plane
#pragma unroll
        for (int j = 0; j < 2; j++) {
            int p = tid + j * 256;
            int row = p >> 2, c = p & 3;
            uint32_t off = (uint32_t)row * ROWB + (uint32_t)c * 16u;
            long arow = bm + row;
            bool ok = arow < N;
            size_t ao = (size_t)(ok ? arow : 0) * K + k0 + c * 8;
            cp16(base + off,           Ahi + ao, ok);
            cp16(base + A_PLANE + off, Alo + ao, ok);
        }
        // B planes: 1024 chunks per plane, 4 per thread per plane
#pragma unroll
        for (int j = 0; j < 4; j++) {
            int p = tid + j * 256;
            int row = p >> 2, c = p & 3;
            uint32_t off = (uint32_t)row * ROWB + (uint32_t)c * 16u;
            size_t bo = (size_t)(bn + row) * K + k0 + c * 8;
            cp16(base + 2 * A_PLANE + off,           Bhi + bo, true);
            cp16(base + 2 * A_PLANE + B_PLANE + off, Blo + bo, true);
        }
    };

    // prologue
    load_stage(0, 0);
    CP_COMMIT();

    const int a_row = wm * 32 + (lane & 15);
    const int a_cc  = (lane >> 4);
    const int b_row = wn * 128 + ((lane >> 4) << 3) + (lane & 7);
    const int b_cc  = ((lane >> 3) & 1);

    for (int i = 0; i < NC; i++) {
        const int pf = i + 1;
        if (pf < NC) load_stage(pf, pf & 1);
        CP_COMMIT();
        asm volatile("cp.async.wait_group 1;" ::: "memory");
        __syncthreads();

        const uint32_t sA  = sb + (i & 1) * STAGEB;
        const uint32_t sAl = sA + A_PLANE;
        const uint32_t sB  = sA + 2 * A_PLANE;
        const uint32_t sBl = sB + B_PLANE;

#pragma unroll
        for (int ks = 0; ks < 2; ks++) {
            uint32_t ah[2][4], al[2][4];
#pragma unroll
            for (int t = 0; t < 2; t++) {
                uint32_t off = (uint32_t)(a_row + t * 16) * ROWB + (uint32_t)(a_cc + ks * 2) * 16u;
                LDSM4(ah[t][0], ah[t][1], ah[t][2], ah[t][3], sA + off);
                LDSM4(al[t][0], al[t][1], al[t][2], al[t][3], sAl + off);
            }
#pragma unroll
            for (int g = 0; g < 8; g++) {
                uint32_t bh[2][2], bl[2][2];
                uint32_t off = (uint32_t)(b_row + g * 16) * ROWB + (uint32_t)(b_cc + ks * 2) * 16u;
                LDSM4(bh[0][0], bh[0][1], bh[1][0], bh[1][1], sB + off);
                LDSM4(bl[0][0], bl[0][1], bl[1][0], bl[1][1], sBl + off);
#pragma unroll
                for (int t = 0; t < 2; t++)
#pragma unroll
                    for (int s2 = 0; s2 < 2; s2++) {
                        MMA16816(acc[t][2 * g + s2], ah[t], bh[s2]);
                        MMA16816(acc[t][2 * g + s2], ah[t], bl[s2]);
                        MMA16816(acc[t][2 * g + s2], al[t], bh[s2]);
                    }
            }
        }
        __syncthreads();
    }

    // epilogue
#pragma unroll
    for (int t = 0; t < 2; t++) {
        const int rbase = bm + wm * 32 + t * 16 + (lane >> 2);
#pragma unroll
        for (int half = 0; half < 2; half++) {
            const long row = rbase + half * 8;
            if (row < N) {
#pragma unroll
                for (int n = 0; n < 16; n++) {
                    const int cb = bn + wn * 128 + n * 8 + (lane & 3) * 2;
                    float2 b2 = *(const float2*)(bias + cb);
                    float vx = acc[t][n][half * 2 + 0] + b2.x;
                    float vy = acc[t][n][half * 2 + 1] + b2.y;
                    if (MODE >= 1) { vx = fmaxf(vx, 0.f); vy = fmaxf(vy, 0.f); }
                    if (MODE == 2) {
                        float2 r2 = *(const float2*)(Radd + row * DO + cb);
                        vx = fmaxf(vx + r2.x, 0.f);
                        vy = fmaxf(vy + r2.y, 0.f);
                    }
                    if (MODE == 1) {
                        __nv_bfloat162 lo2;
                        __nv_bfloat162 hi2 = split_hi2(vx, vy, lo2);
                        size_t o = ((size_t)row * DO + cb) >> 1;
                        Chi[o] = hi2;
                        Clo[o] = lo2;
                    } else {
                        float2 o; o.x = vx; o.y = vy;
                        *(float2*)(C + row * DO + cb) = o;
                    }
                }
            }
        }
    }
}

// ---------------- row LayerNorm (optionally emits split planes) -------------
__global__ void ln_kernel(const float* __restrict__ in, const float* __restrict__ gam,
                          const float* __restrict__ bet, float* __restrict__ out,
                          __nv_bfloat162* __restrict__ ohi, __nv_bfloat162* __restrict__ olo,
                          int D) {
    const int row = blockIdx.x;
    const float4* ip = (const float4*)(in + (size_t)row * D);
    float4* op = (float4*)(out + (size_t)row * D);
    const int nv = D >> 2;
    float4 v[4];
    int cnt = 0;
    float s = 0.f, ss = 0.f;
    for (int i = threadIdx.x; i < nv; i += 256) {
        float4 x = ip[i];
        v[cnt++] = x;
        s  += x.x + x.y + x.z + x.w;
        ss += x.x * x.x + x.y * x.y + x.z * x.z + x.w * x.w;
    }
#pragma unroll
    for (int o = 16; o; o >>= 1) {
        s  += __shfl_xor_sync(0xffffffffu, s, o);
        ss += __shfl_xor_sync(0xffffffffu, ss, o);
    }
    __shared__ float rs[8], rss[8], stats[2];
    const int w = threadIdx.x >> 5, l = threadIdx.x & 31;
    if (l == 0) { rs[w] = s; rss[w] = ss; }
    __syncthreads();
    if (threadIdx.x < 32) {
        float a = (threadIdx.x < 8) ? rs[threadIdx.x]  : 0.f;
        float b = (threadIdx.x < 8) ? rss[threadIdx.x] : 0.f;
#pragma unroll
        for (int o = 4; o; o >>= 1) {
            a += __shfl_xor_sync(0xffffffffu, a, o);
            b += __shfl_xor_sync(0xffffffffu, b, o);
        }
        if (threadIdx.x == 0) {
            float mu  = a / (float)D;
            float var = b / (float)D - mu * mu;
            stats[0] = mu;
            stats[1] = rsqrtf(var + 1e-5f);
        }
    }
    __syncthreads();
    const float mu = stats[0], inv = stats[1];
    cnt = 0;
    for (int i = threadIdx.x; i < nv; i += 256) {
        float4 x = v[cnt++];
        float4 g = ((const float4*)gam)[i];
        float4 b = ((const float4*)bet)[i];
        float4 o;
        o.x = (x.x - mu) * inv * g.x + b.x;
        o.y = (x.y - mu) * inv * g.y + b.y;
        o.z = (x.z - mu) * inv * g.z + b.z;
        o.w = (x.w - mu) * inv * g.w + b.w;
        op[i] = o;
        if (ohi) {
            __nv_bfloat162 l0, l1;
            __nv_bfloat162 h0 = split_hi2(o.x, o.y, l0);
            __nv_bfloat162 h1 = split_hi2(o.z, o.w, l1);
            size_t base = (size_t)row * (D >> 1) + i * 2;
            ohi[base] = h0; ohi[base + 1] = h1;
            olo[base] = l0; olo[base + 1] = l1;
        }
    }
}

// ---------------- host orchestration ----------------------------------------
template <int MODE>
static void launch_gemm(const __nv_bfloat16* ahi, const __nv_bfloat16* alo,
                        const __nv_bfloat16* bhi, const __nv_bfloat16* blo,
                        const float* bias, const float* radd, float* c,
                        __nv_bfloat16* chi, __nv_bfloat16* clo, int K, int DO) {
    dim3 grid((N_NODES + 127) / 128, DO / 256);
    hmma_gemm_kernel<MODE><<<grid, 256, GEMM_SMEM>>>(
        ahi, alo, bhi, blo, bias, radd, c,
        (__nv_bfloat162*)chi, (__nv_bfloat162*)clo, N_NODES, K, DO);
}

extern "C" void kernel_launch(void* const* d_in, const int* in_sizes, int n_in,
                              void* d_out, int out_size) {
    const float* x   = (const float*)d_in[0];
    const int*   ei  = (const int*)d_in[1];
    const float* w1a = (const float*)d_in[2];
    const float* b1a = (const float*)d_in[3];
    const float* w1b = (const float*)d_in[4];
    const float* b1b = (const float*)d_in[5];
    const float* w2a = (const float*)d_in[6];
    const float* b2a = (const float*)d_in[7];
    const float* w2b = (const float*)d_in[8];
    const float* b2b = (const float*)d_in[9];
    const float* w3a = (const float*)d_in[10];
    const float* b3a = (const float*)d_in[11];
    const float* w3b = (const float*)d_in[12];
    const float* b3b = (const float*)d_in[13];
    const float* rp1w = (const float*)d_in[14];
    const float* rp1b = (const float*)d_in[15];
    const float* rp2w = (const float*)d_in[16];
    const float* rp2b = (const float*)d_in[17];
    const float* rp3w = (const float*)d_in[18];
    const float* rp3b = (const float*)d_in[19];
    const float* ln1g = (const float*)d_in[20];
    const float* ln1b = (const float*)d_in[21];
    const float* ln2g = (const float*)d_in[22];
    const float* ln2b = (const float*)d_in[23];
    const float* ln3g = (const float*)d_in[24];
    const float* ln3b = (const float*)d_in[25];
    float* out = (float*)d_out;

    float *z, *r, *h;
    __nv_bfloat16 *a1hi, *a1lo, *a2hi, *a2lo, *a3hi, *a3lo, *whi, *wlo;
    int *csr_cnt, *csr_off, *csr_cur, *esrc, *bsum;
    cudaGetSymbolAddress((void**)&z, g_z);
    cudaGetSymbolAddress((void**)&r, g_r);
    cudaGetSymbolAddress((void**)&h, g_h);
    cudaGetSymbolAddress((void**)&a1hi, g_a1hi);
    cudaGetSymbolAddress((void**)&a1lo, g_a1lo);
    cudaGetSymbolAddress((void**)&a2hi, g_a2hi);
    cudaGetSymbolAddress((void**)&a2lo, g_a2lo);
    cudaGetSymbolAddress((void**)&a3hi, g_a3hi);
    cudaGetSymbolAddress((void**)&a3lo, g_a3lo);
    cudaGetSymbolAddress((void**)&whi, g_whi);
    cudaGetSymbolAddress((void**)&wlo, g_wlo);
    cudaGetSymbolAddress((void**)&csr_cnt, g_cnt);
    cudaGetSymbolAddress((void**)&csr_off, g_off);
    cudaGetSymbolAddress((void**)&csr_cur, g_cur);
    cudaGetSymbolAddress((void**)&esrc, g_esrc);
    cudaGetSymbolAddress((void**)&bsum, g_bsum);

    cudaFuncSetAttribute(hmma_gemm_kernel<0>, cudaFuncAttributeMaxDynamicSharedMemorySize, GEMM_SMEM);
    cudaFuncSetAttribute(hmma_gemm_kernel<1>, cudaFuncAttributeMaxDynamicSharedMemorySize, GEMM_SMEM);
    cudaFuncSetAttribute(hmma_gemm_kernel<2>, cudaFuncAttributeMaxDynamicSharedMemorySize, GEMM_SMEM);

    // ---- CSR build (once per call) ----
    const int NB = (N_NODES + 255) / 256;
    const int EB = (N_EDGES + 255) / 256;
    csr_zero<<<NB, 256>>>(csr_cnt, csr_cur);
    csr_hist<<<EB, 256>>>(ei, csr_cnt);
    csr_scan1<<<NB, 256>>>(csr_cnt, csr_off, bsum);
    csr_scan2<<<1, 256>>>(bsum, NB);
    csr_scan3<<<NB, 256>>>(csr_off, bsum);
    csr_fill<<<EB, 256>>>(ei, csr_off, csr_cur, esrc);

    // ---- weight split (once per call) ----
    const size_t o_w1a = 0;
    const size_t o_w1b = o_w1a + 128 * 256;
    const size_t o_rp1 = o_w1b + 256 * 256;
    const size_t o_w2a = o_rp1 + 128 * 256;
    const size_t o_w2b = o_w2a + 256 * 512;
    const size_t o_rp2 = o_w2b + 512 * 512;
    const size_t o_w3a = o_rp2 + 256 * 512;
    const size_t o_w3b = o_w3a + 512 * 1024;
    const size_t o_rp3 = o_w3b + 1024 * 1024;

    struct WS { const float* w; size_t off; int K, DO; };
    const WS ws[9] = {
        {w1a, o_w1a, 128, 256},  {w1b, o_w1b, 256, 256},   {rp1w, o_rp1, 128, 256},
        {w2a, o_w2a, 256, 512},  {w2b, o_w2b, 512, 512},   {rp2w, o_rp2, 256, 512},
        {w3a, o_w3a, 512, 1024}, {w3b, o_w3b, 1024, 1024}, {rp3w, o_rp3, 512, 1024},
    };
    for (int i = 0; i < 9; i++) {
        dim3 g(ws[i].DO / 32, ws[i].K / 32), b(32, 32);
        wsplit_kernel<<<g, b>>>(ws[i].w, whi + ws[i].off, wlo + ws[i].off, ws[i].K, ws[i].DO);
    }

    // residual input split for block 1 (x)
    {
        long n4 = (long)N_NODES * 128 / 4;
        asplit_kernel<<<(unsigned)((n4 + 255) / 256), 256>>>(
            (const float4*)x, (__nv_bfloat162*)a2hi, (__nv_bfloat162*)a2lo, n4);
    }

    // ---- block 1: 128 -> 256 ----
    aggregate_kernel<128><<<(N_NODES + 3) / 4, 128>>>(x, csr_off, csr_cnt, esrc,
                                                      (__nv_bfloat162*)a1hi, (__nv_bfloat162*)a1lo);
    launch_gemm<1>(a1hi, a1lo, whi + o_w1a, wlo + o_w1a, b1a, nullptr, nullptr, a3hi, a3lo, 128, 256);
    launch_gemm<0>(a2hi, a2lo, whi + o_rp1, wlo + o_rp1, rp1b, nullptr, r, nullptr, nullptr, 128, 256);
    launch_gemm<2>(a3hi, a3lo, whi + o_w1b, wlo + o_w1b, b1b, r, z, nullptr, nullptr, 256, 256);
    ln_kernel<<<N_NODES, 256>>>(z, ln1g, ln1b, h, (__nv_bfloat162*)a2hi, (__nv_bfloat162*)a2lo, 256);

    // ---- block 2: 256 -> 512 ----
    aggregate_kernel<256><<<(N_NODES + 1) / 2, 128>>>(h, csr_off, csr_cnt, esrc,
                                                      (__nv_bfloat162*)a1hi, (__nv_bfloat162*)a1lo);
    launch_gemm<1>(a1hi, a1lo, whi + o_w2a, wlo + o_w2a, b2a, nullptr, nullptr, a3hi, a3lo, 256, 512);
    launch_gemm<0>(a2hi, a2lo, whi + o_rp2, wlo + o_rp2, rp2b, nullptr, r, nullptr, nullptr, 256, 512);
    launch_gemm<2>(a3hi, a3lo, whi + o_w2b, wlo + o_w2b, b2b, r, z, nullptr, nullptr, 512, 512);
    ln_kernel<<<N_NODES, 256>>>(z, ln2g, ln2b, h, (__nv_bfloat162*)a2hi, (__nv_bfloat162*)a2lo, 512);

    // ---- block 3: 512 -> 1024 ----
    aggregate_kernel<512><<<N_NODES, 128>>>(h, csr_off, csr_cnt, esrc,
                                            (__nv_bfloat162*)a1hi, (__nv_bfloat162*)a1lo);
    launch_gemm<1>(a1hi, a1lo, whi + o_w3a, wlo + o_w3a, b3a, nullptr, nullptr, a3hi, a3lo, 512, 1024);
    launch_gemm<0>(a2hi, a2lo, whi + o_rp3, wlo + o_rp3, rp3b, nullptr, r, nullptr, nullptr, 512, 1024);
    launch_gemm<2>(a3hi, a3lo, whi + o_w3b, wlo + o_w3b, b3b, r, z, nullptr, nullptr, 1024, 1024);
    ln_kernel<<<N_NODES, 256>>>(z, ln3g, ln3b, out, nullptr, nullptr, 1024);
}